// round 4
// baseline (speedup 1.0000x reference)
#include <cuda_runtime.h>

#define N_USERS   50000
#define N_ITEMS   30000
#define N_ENT     100000
#define N_REL     50
#define N_EDGES   1500000
#define N_INTER   1000000
#define D         64
#define GAMMA_F   0.1f

// scan partition: 2048 elems per block
#define PB0 49   // ceil(N_ENT/2048)
#define PB1 25   // ceil(N_USERS/2048)
#define PB2 15   // ceil(N_ITEMS/2048)
#define PBT (PB0 + PB1 + PB2)

// iter3 smem cache: CAP edges per warp, padded row stride (bank-conflict-free)
#define CAP 24
#define RS  68
#define ITER_SMEM (2 * 8 * CAP * RS * 4)   // 104448 bytes

// ---------------- static device scratch ----------------
__device__ int   g_bins_e[N_ENT];
__device__ int   g_bins_r[N_USERS];
__device__ int   g_bins_c[N_ITEMS];
__device__ int   g_cur_e[N_ENT];
__device__ int   g_cur_r[N_USERS];
__device__ int   g_cur_c[N_ITEMS];
__device__ int   g_eoff[N_ENT + 1];
__device__ int   g_roff[N_USERS + 1];
__device__ int   g_coff[N_ITEMS + 1];
__device__ int   g_part[PBT];
__device__ int2  g_te[N_EDGES];        // (tail, rel)
__device__ int2  g_rc[N_INTER];        // (col, orig idx)
__device__ int   g_crow[N_INTER];
__device__ float g_W1t[D * D];         // transposed [k][d]
__device__ float g_W2t[D * D];
__device__ float g_wkg[N_ITEMS * D];
__device__ float g_cu[N_INTER];
__device__ float g_cc[N_INTER];

__device__ __forceinline__ float fsigmoid(float x) {
    return __fdividef(1.f, 1.f + __expf(-x));
}

// ---------------- setup: zero bins + transpose W ----------------
__global__ void zero3_kernel(const float* __restrict__ W1, const float* __restrict__ W2) {
    int i = blockIdx.x * blockDim.x + threadIdx.x;
    if (i < N_ENT)   g_bins_e[i] = 0;
    if (i < N_USERS) g_bins_r[i] = 0;
    if (i < N_ITEMS) g_bins_c[i] = 0;
    if (i < D * D) {
        int d = i >> 6, k = i & 63;
        g_W1t[(k << 6) + d] = W1[i];
        g_W2t[(k << 6) + d] = W2[i];
    }
}

__global__ void hist3_kernel(const int* __restrict__ head,
                             const int2* __restrict__ imat) {
    int i = blockIdx.x * blockDim.x + threadIdx.x;
    if (i < N_EDGES) atomicAdd(&g_bins_e[head[i]], 1);
    if (i < N_INTER) {
        int2 rc = imat[i];
        atomicAdd(&g_bins_r[rc.x], 1);
        atomicAdd(&g_bins_c[rc.y], 1);
    }
}

// ---------------- 2-phase multi-block scan ----------------
__device__ __forceinline__ void scan_map(int b, int& which, int& lb) {
    which = (b < PB0) ? 0 : (b < PB0 + PB1) ? 1 : 2;
    lb = b - ((which == 0) ? 0 : (which == 1) ? PB0 : PB0 + PB1);
}

__global__ void __launch_bounds__(256) scanA_kernel() {
    int which, lb;
    scan_map(blockIdx.x, which, lb);
    int n = (which == 0) ? N_ENT : (which == 1) ? N_USERS : N_ITEMS;
    const int* bins = (which == 0) ? g_bins_e : (which == 1) ? g_bins_r : g_bins_c;
    int base = lb * 2048;
    int sum = 0;
    for (int i = threadIdx.x; i < 2048; i += 256) {
        int idx = base + i;
        sum += (idx < n) ? bins[idx] : 0;
    }
    #pragma unroll
    for (int o = 16; o; o >>= 1) sum += __shfl_xor_sync(0xffffffffu, sum, o);
    __shared__ int ws[8];
    int lane = threadIdx.x & 31, wid = threadIdx.x >> 5;
    if (lane == 0) ws[wid] = sum;
    __syncthreads();
    if (threadIdx.x == 0) {
        int t = 0;
        #pragma unroll
        for (int i = 0; i < 8; i++) t += ws[i];
        g_part[blockIdx.x] = t;
    }
}

// scanC: per-block prefix over raw partials (scanB folded in)
__global__ void __launch_bounds__(256) scanC_kernel() {
    int which, lb;
    scan_map(blockIdx.x, which, lb);
    int n  = (which == 0) ? N_ENT : (which == 1) ? N_USERS : N_ITEMS;
    int nb = (which == 0) ? PB0   : (which == 1) ? PB1     : PB2;
    int pbase = (which == 0) ? 0  : (which == 1) ? PB0     : PB0 + PB1;
    const int* bins = (which == 0) ? g_bins_e : (which == 1) ? g_bins_r : g_bins_c;
    int* offs = (which == 0) ? g_eoff : (which == 1) ? g_roff : g_coff;
    int* cur  = (which == 0) ? g_cur_e : (which == 1) ? g_cur_r : g_cur_c;
    int base = lb * 2048;
    int lane = threadIdx.x & 31, wid = threadIdx.x >> 5;

    __shared__ int s_pref;
    if (wid == 0) {
        int p = 0;
        for (int i = lane; i < lb; i += 32) p += g_part[pbase + i];
        #pragma unroll
        for (int o = 16; o; o >>= 1) p += __shfl_xor_sync(0xffffffffu, p, o);
        if (lane == 0) {
            s_pref = p;
            if (lb == nb - 1) offs[n] = p + g_part[pbase + lb];
        }
    }

    int vals[8];
    int tsum = 0;
    #pragma unroll
    for (int k = 0; k < 8; k++) {
        int idx = base + threadIdx.x * 8 + k;
        vals[k] = (idx < n) ? bins[idx] : 0;
        tsum += vals[k];
    }
    int x = tsum;
    #pragma unroll
    for (int o = 1; o < 32; o <<= 1) {
        int t = __shfl_up_sync(0xffffffffu, x, o);
        if (lane >= o) x += t;
    }
    __shared__ int ws[8];
    if (lane == 31) ws[wid] = x;
    __syncthreads();
    int wpref = 0;
    for (int i = 0; i < wid; i++) wpref += ws[i];
    int acc = s_pref + wpref + x - tsum;
    #pragma unroll
    for (int k = 0; k < 8; k++) {
        int idx = base + threadIdx.x * 8 + k;
        if (idx < n) { offs[idx] = acc; cur[idx] = acc; }
        acc += vals[k];
    }
}

__global__ void scatter3_kernel(const int* __restrict__ head,
                                const int* __restrict__ tail,
                                const int* __restrict__ etype,
                                const int2* __restrict__ imat) {
    int i = blockIdx.x * blockDim.x + threadIdx.x;
    if (i < N_EDGES) {
        int h = head[i];
        int pos = atomicAdd(&g_cur_e[h], 1);
        g_te[pos] = make_int2(tail[i], etype[i]);
    }
    if (i < N_INTER) {
        int2 rc = imat[i];
        int pr = atomicAdd(&g_cur_r[rc.x], 1);
        g_rc[pr] = make_int2(rc.y, i);
        int pc = atomicAdd(&g_cur_c[rc.y], 1);
        g_crow[pc] = rc.x;
    }
}

// ---------------- KG aggregation (2 entities/warp) + item_agg fused ----------------
#define EBLK 6250   // 100000 entities / 16 per block
#define IBLK 3750   // 30000 items / 8 per block

__global__ void __launch_bounds__(256) entity_item_kernel(
    const float* __restrict__ ent, const float* __restrict__ relw,
    const float* __restrict__ b1, const float* __restrict__ b2,
    const float* __restrict__ ucf0,
    float* __restrict__ out_agg, float* __restrict__ out_item)
{
    int tid = threadIdx.x;
    int warp = tid >> 5, lane = tid & 31, hl = lane >> 4, q = lane & 15;

    if (blockIdx.x >= EBLK) {
        // -------- item_agg path --------
        int it = (blockIdx.x - EBLK) * 8 + warp;
        int s = g_coff[it], e = g_coff[it + 1];
        float4 acc = make_float4(0.f, 0.f, 0.f, 0.f);
        int j = s;
        #pragma unroll 2
        for (; j + 2 <= e; j += 2) {
            int r = g_crow[j + hl];
            float4 v = *(const float4*)&ucf0[(size_t)r * D + q * 4];
            acc.x += v.x; acc.y += v.y; acc.z += v.z; acc.w += v.w;
        }
        if (j < e && hl == 0) {
            int r = g_crow[j];
            float4 v = *(const float4*)&ucf0[(size_t)r * D + q * 4];
            acc.x += v.x; acc.y += v.y; acc.z += v.z; acc.w += v.w;
        }
        acc.x += __shfl_xor_sync(0xffffffffu, acc.x, 16);
        acc.y += __shfl_xor_sync(0xffffffffu, acc.y, 16);
        acc.z += __shfl_xor_sync(0xffffffffu, acc.z, 16);
        acc.w += __shfl_xor_sync(0xffffffffu, acc.w, 16);
        if (hl == 0) {
            float inv = 1.f / fmaxf((float)(e - s), 1.f);
            float4 r = make_float4(acc.x * inv, acc.y * inv, acc.z * inv, acc.w * inv);
            *(float4*)&out_item[(size_t)it * D + q * 4] = r;
        }
        return;
    }

    // -------- entity path --------
    __shared__ float sRel[N_REL * D];
    __shared__ float sMA[8][2][D];
    __shared__ float sMB[8][2][D];
    for (int i = tid; i < N_REL * D; i += 256) sRel[i] = relw[i];
    __syncthreads();

    int h = blockIdx.x * 16 + warp * 2 + hl;
    int s = g_eoff[h], e = g_eoff[h + 1];
    bool head_item = (h < N_ITEMS);

    float4 a1 = make_float4(0.f, 0.f, 0.f, 0.f), a2 = a1, ar = a1;
    int c1 = 0, c2 = 0;
    #pragma unroll 2
    for (int j = s; j < e; j++) {
        int2 tr = g_te[j];
        float4 te = *(const float4*)&ent[(size_t)tr.x * D + q * 4];
        float4 re = *(const float4*)&sRel[tr.y * D + q * 4];
        ar.x += re.x; ar.y += re.y; ar.z += re.z; ar.w += re.w;
        bool cross = head_item ^ (tr.x < N_ITEMS);
        if (cross) {
            a1.x += te.x * re.x; a1.y += te.y * re.y;
            a1.z += te.z * re.z; a1.w += te.w * re.w; c1++;
        } else {
            a2.x += te.x + re.x; a2.y += te.y + re.y;
            a2.z += te.z + re.z; a2.w += te.w + re.w; c2++;
        }
    }
    float inv1 = 1.f / fmaxf((float)c1, 1.f);
    float inv2 = 1.f / fmaxf((float)c2, 1.f);
    float invr = 1.f / fmaxf((float)(e - s), 1.f);

    if (head_item) {
        float4 kg = *(const float4*)&ent[(size_t)h * D + q * 4];
        float4 w = make_float4(ar.x * invr * kg.x, ar.y * invr * kg.y,
                               ar.z * invr * kg.z, ar.w * invr * kg.w);
        *(float4*)&g_wkg[(size_t)h * D + q * 4] = w;
    }

    *(float4*)&sMA[warp][hl][q * 4] = make_float4(a1.x * inv1, a1.y * inv1, a1.z * inv1, a1.w * inv1);
    *(float4*)&sMB[warp][hl][q * 4] = make_float4(a2.x * inv2, a2.y * inv2, a2.z * inv2, a2.w * inv2);
    __syncwarp();

    float4 o = *(const float4*)&b1[q * 4];
    float4 p = *(const float4*)&b2[q * 4];
    #pragma unroll 8
    for (int k = 0; k < D; k++) {
        float m1 = sMA[warp][hl][k];
        float m2 = sMB[warp][hl][k];
        float4 w1 = *(const float4*)&g_W1t[k * D + q * 4];
        float4 w2 = *(const float4*)&g_W2t[k * D + q * 4];
        o.x += m1 * w1.x; o.y += m1 * w1.y; o.z += m1 * w1.z; o.w += m1 * w1.w;
        p.x += m2 * w2.x; p.y += m2 * w2.y; p.z += m2 * w2.z; p.w += m2 * w2.w;
    }
    float4 r;
    r.x = (o.x >= 0.f ? o.x : 0.01f * o.x) * 0.5f + (p.x >= 0.f ? p.x : 0.01f * p.x) * 0.5f;
    r.y = (o.y >= 0.f ? o.y : 0.01f * o.y) * 0.5f + (p.y >= 0.f ? p.y : 0.01f * p.y) * 0.5f;
    r.z = (o.z >= 0.f ? o.z : 0.01f * o.z) * 0.5f + (p.z >= 0.f ? p.z : 0.01f * p.z) * 0.5f;
    r.w = (o.w >= 0.f ? o.w : 0.01f * o.w) * 0.5f + (p.w >= 0.f ? p.w : 0.01f * p.w) * 0.5f;
    *(float4*)&out_agg[(size_t)h * D + q * 4] = r;
}

// ---------------- fused 3-iteration CF attention with smem row cache ----------------
__global__ void __launch_bounds__(256) iter3_kernel(
    const float* __restrict__ user, const float* __restrict__ ucf0,
    const float* __restrict__ ent,  const float* __restrict__ icf,
    float* __restrict__ out_u, float* __restrict__ out_ucf,
    float* __restrict__ out_mask)
{
    extern __shared__ float sm[];
    int warp = threadIdx.x >> 5, lane = threadIdx.x & 31;
    int hl = lane >> 4, q = lane & 15;
    float* sI = sm + warp * (CAP * RS);                 // icf cache
    float* sE = sm + (8 + warp) * (CAP * RS);           // ent cache

    int gw = blockIdx.x * 8 + warp;     // 6250*8 = 50000 exact
    int s = g_roff[gw], e = g_roff[gw + 1];

    float4 u = *(const float4*)&user[(size_t)gw * D + q * 4];
    float4 c = *(const float4*)&ucf0[(size_t)gw * D + q * 4];

    #pragma unroll 1
    for (int it = 0; it < 3; it++) {
        // ---- pass 1: dots + softmax numerators ----
        float z = 0.f, zc = 0.f;
        int j = s;
        #pragma unroll 2
        for (; j + 2 <= e; j += 2) {
            int local = j + hl - s;
            int col = g_rc[j + hl].x;
            float4 w = *(const float4*)&g_wkg[(size_t)col * D + q * 4];
            float4 v;
            if (it == 0) {
                v = *(const float4*)&icf[(size_t)col * D + q * 4];
                if (local < CAP) *(float4*)&sI[local * RS + q * 4] = v;
            } else {
                if (local < CAP) v = *(const float4*)&sI[local * RS + q * 4];
                else             v = *(const float4*)&icf[(size_t)col * D + q * 4];
            }
            float d1 = u.x * w.x + u.y * w.y + u.z * w.z + u.w * w.w;
            float d2 = c.x * v.x + c.y * v.y + c.z * v.z + c.w * v.w;
            #pragma unroll
            for (int o = 8; o; o >>= 1) {
                d1 += __shfl_xor_sync(0xffffffffu, d1, o);
                d2 += __shfl_xor_sync(0xffffffffu, d2, o);
            }
            if (q == 0) {
                float ep = __expf(fsigmoid(d1));
                float eq = __expf(fsigmoid(d2));
                z += ep; zc += eq;
                g_cu[j + hl] = ep;
                g_cc[j + hl] = eq;
            }
        }
        if (j < e) {
            int local = j - s;
            int col = g_rc[j].x;
            float4 w = *(const float4*)&g_wkg[(size_t)col * D + q * 4];
            float4 v;
            if (it == 0) {
                v = *(const float4*)&icf[(size_t)col * D + q * 4];
                if (local < CAP && hl == 0) *(float4*)&sI[local * RS + q * 4] = v;
            } else {
                if (local < CAP) v = *(const float4*)&sI[local * RS + q * 4];
                else             v = *(const float4*)&icf[(size_t)col * D + q * 4];
            }
            float d1 = u.x * w.x + u.y * w.y + u.z * w.z + u.w * w.w;
            float d2 = c.x * v.x + c.y * v.y + c.z * v.z + c.w * v.w;
            #pragma unroll
            for (int o = 8; o; o >>= 1) {
                d1 += __shfl_xor_sync(0xffffffffu, d1, o);
                d2 += __shfl_xor_sync(0xffffffffu, d2, o);
            }
            if (lane == 0) {
                float ep = __expf(fsigmoid(d1));
                float eq = __expf(fsigmoid(d2));
                z += ep; zc += eq;
                g_cu[j] = ep;
                g_cc[j] = eq;
            }
        }
        __syncwarp();
        #pragma unroll
        for (int o = 16; o; o >>= 1) {
            z  += __shfl_xor_sync(0xffffffffu, z, o);
            zc += __shfl_xor_sync(0xffffffffu, zc, o);
        }
        float iz  = (z  > 0.f) ? __fdividef(1.f, z)  : 0.f;
        float izc = (zc > 0.f) ? __fdividef(1.f, zc) : 0.f;

        // ---- mid: lane-parallel coefficients + mask ----
        for (int jj = s + lane; jj < e; jj += 32) {
            float pn = g_cu[jj] * iz;
            float qn = g_cc[jj] * izc;
            float m = (fabsf(fsigmoid(pn) - fsigmoid(qn)) < GAMMA_F) ? 1.f : 0.f;
            if (it == 2) out_mask[g_rc[jj].y] = m;
            g_cu[jj] = pn * m;
            g_cc[jj] = qn * m;
        }
        __syncwarp();

        // ---- pass 2: weighted sums ----
        float4 au = make_float4(0.f, 0.f, 0.f, 0.f), ac = au;
        j = s;
        #pragma unroll 2
        for (; j + 2 <= e; j += 2) {
            int jj = j + hl;
            int local = jj - s;
            int col = g_rc[jj].x;
            float cu = g_cu[jj], cc = g_cc[jj];
            float4 kg, v;
            if (it == 0) {
                kg = *(const float4*)&ent[(size_t)col * D + q * 4];
                if (local < CAP) *(float4*)&sE[local * RS + q * 4] = kg;
            } else {
                if (local < CAP) kg = *(const float4*)&sE[local * RS + q * 4];
                else             kg = *(const float4*)&ent[(size_t)col * D + q * 4];
            }
            if (local < CAP) v = *(const float4*)&sI[local * RS + q * 4];
            else             v = *(const float4*)&icf[(size_t)col * D + q * 4];
            au.x += cu * kg.x; au.y += cu * kg.y; au.z += cu * kg.z; au.w += cu * kg.w;
            ac.x += cc * v.x;  ac.y += cc * v.y;  ac.z += cc * v.z;  ac.w += cc * v.w;
        }
        if (j < e && hl == 0) {
            int local = j - s;
            int col = g_rc[j].x;
            float cu = g_cu[j], cc = g_cc[j];
            float4 kg, v;
            if (it == 0) {
                kg = *(const float4*)&ent[(size_t)col * D + q * 4];
                if (local < CAP) *(float4*)&sE[local * RS + q * 4] = kg;
            } else {
                if (local < CAP) kg = *(const float4*)&sE[local * RS + q * 4];
                else             kg = *(const float4*)&ent[(size_t)col * D + q * 4];
            }
            if (local < CAP) v = *(const float4*)&sI[local * RS + q * 4];
            else             v = *(const float4*)&icf[(size_t)col * D + q * 4];
            au.x += cu * kg.x; au.y += cu * kg.y; au.z += cu * kg.z; au.w += cu * kg.w;
            ac.x += cc * v.x;  ac.y += cc * v.y;  ac.z += cc * v.z;  ac.w += cc * v.w;
        }
        au.x += __shfl_xor_sync(0xffffffffu, au.x, 16);
        au.y += __shfl_xor_sync(0xffffffffu, au.y, 16);
        au.z += __shfl_xor_sync(0xffffffffu, au.z, 16);
        au.w += __shfl_xor_sync(0xffffffffu, au.w, 16);
        ac.x += __shfl_xor_sync(0xffffffffu, ac.x, 16);
        ac.y += __shfl_xor_sync(0xffffffffu, ac.y, 16);
        ac.z += __shfl_xor_sync(0xffffffffu, ac.z, 16);
        ac.w += __shfl_xor_sync(0xffffffffu, ac.w, 16);

        if (it < 2) {
            float su = au.x * au.x + au.y * au.y + au.z * au.z + au.w * au.w;
            float sc = ac.x * ac.x + ac.y * ac.y + ac.z * ac.z + ac.w * ac.w;
            #pragma unroll
            for (int o = 8; o; o >>= 1) {
                su += __shfl_xor_sync(0xffffffffu, su, o);
                sc += __shfl_xor_sync(0xffffffffu, sc, o);
            }
            float inu = __fdividef(1.f, fmaxf(sqrtf(su), 1e-12f));
            float inc = __fdividef(1.f, fmaxf(sqrtf(sc), 1e-12f));
            u.x = au.x * inu; u.y = au.y * inu; u.z = au.z * inu; u.w = au.w * inu;
            c.x = ac.x * inc; c.y = ac.y * inc; c.z = ac.z * inc; c.w = ac.w * inc;
        } else if (hl == 0) {
            *(float4*)&out_u[(size_t)gw * D + q * 4]   = au;
            *(float4*)&out_ucf[(size_t)gw * D + q * 4] = ac;
        }
        __syncwarp();
    }
}

// ---------------- launch ----------------
extern "C" void kernel_launch(void* const* d_in, const int* in_sizes, int n_in,
                              void* d_out, int out_size) {
    const float* ent   = (const float*)d_in[0];
    const float* user  = (const float*)d_in[1];
    const float* ucf   = (const float*)d_in[2];
    const float* icf   = (const float*)d_in[3];
    const float* relw  = (const float*)d_in[4];
    const float* W1    = (const float*)d_in[5];
    const float* b1    = (const float*)d_in[6];
    const float* W2    = (const float*)d_in[7];
    const float* b2    = (const float*)d_in[8];
    const int*   eidx  = (const int*)d_in[9];     // [2, N_EDGES]
    const int*   etype = (const int*)d_in[10];
    const int*   imat  = (const int*)d_in[11];    // [N_INTER, 2]

    float* out      = (float*)d_out;
    float* out_ent  = out;
    float* out_u    = out_ent + (size_t)N_ENT * D;
    float* out_ucf  = out_u   + (size_t)N_USERS * D;
    float* out_item = out_ucf + (size_t)N_USERS * D;
    float* out_mask = out_item + (size_t)N_ITEMS * D;

    static int attr_set = 0;
    if (!attr_set) {
        cudaFuncSetAttribute(iter3_kernel,
                             cudaFuncAttributeMaxDynamicSharedMemorySize, ITER_SMEM);
        attr_set = 1;
    }

    const int T = 256;
    zero3_kernel<<<(N_ENT + T - 1) / T, T>>>(W1, W2);
    hist3_kernel<<<(N_EDGES + T - 1) / T, T>>>(eidx, (const int2*)imat);
    scanA_kernel<<<PBT, T>>>();
    scanC_kernel<<<PBT, T>>>();
    scatter3_kernel<<<(N_EDGES + T - 1) / T, T>>>(eidx, eidx + N_EDGES, etype,
                                                  (const int2*)imat);

    entity_item_kernel<<<EBLK + IBLK, T>>>(ent, relw, b1, b2, ucf,
                                           out_ent, out_item);

    iter3_kernel<<<N_USERS / 8, T, ITER_SMEM>>>(user, ucf, ent, icf,
                                                out_u, out_ucf, out_mask);
}

// round 5
// speedup vs baseline: 1.8804x; 1.8804x over previous
#include <cuda_runtime.h>

#define N_USERS   50000
#define N_ITEMS   30000
#define N_ENT     100000
#define N_REL     50
#define N_EDGES   1500000
#define N_INTER   1000000
#define D         64
#define GAMMA_F   0.1f

// scan partition: 2048 elems per block
#define PB0 49   // ceil(N_ENT/2048)
#define PB1 25   // ceil(N_USERS/2048)
#define PB2 15   // ceil(N_ITEMS/2048)
#define PBT (PB0 + PB1 + PB2)

// ---------------- static device scratch ----------------
__device__ int   g_bins_e[N_ENT];
__device__ int   g_bins_r[N_USERS];
__device__ int   g_bins_c[N_ITEMS];
__device__ int   g_cur_e[N_ENT];
__device__ int   g_cur_r[N_USERS];
__device__ int   g_cur_c[N_ITEMS];
__device__ int   g_eoff[N_ENT + 1];
__device__ int   g_roff[N_USERS + 1];
__device__ int   g_coff[N_ITEMS + 1];
__device__ int   g_part[PBT];
__device__ int2  g_te[N_EDGES];        // (tail, rel)
__device__ int2  g_rc[N_INTER];        // (col, orig idx)
__device__ int   g_crow[N_INTER];
__device__ float g_W1t[D * D];         // transposed [k][d]
__device__ float g_W2t[D * D];
__device__ float g_wkg[N_ITEMS * D];
__device__ float g_cu[N_INTER];
__device__ float g_cc[N_INTER];

__device__ __forceinline__ float fsigmoid(float x) {
    return __fdividef(1.f, 1.f + __expf(-x));
}

// ---------------- setup: zero bins + transpose W ----------------
__global__ void zero3_kernel(const float* __restrict__ W1, const float* __restrict__ W2) {
    int i = blockIdx.x * blockDim.x + threadIdx.x;
    if (i < N_ENT)   g_bins_e[i] = 0;
    if (i < N_USERS) g_bins_r[i] = 0;
    if (i < N_ITEMS) g_bins_c[i] = 0;
    if (i < D * D) {
        int d = i >> 6, k = i & 63;
        g_W1t[(k << 6) + d] = W1[i];
        g_W2t[(k << 6) + d] = W2[i];
    }
}

__global__ void hist3_kernel(const int* __restrict__ head,
                             const int2* __restrict__ imat) {
    int i = blockIdx.x * blockDim.x + threadIdx.x;
    if (i < N_EDGES) atomicAdd(&g_bins_e[head[i]], 1);
    if (i < N_INTER) {
        int2 rc = imat[i];
        atomicAdd(&g_bins_r[rc.x], 1);
        atomicAdd(&g_bins_c[rc.y], 1);
    }
}

// ---------------- 2-phase multi-block scan ----------------
__device__ __forceinline__ void scan_map(int b, int& which, int& lb) {
    which = (b < PB0) ? 0 : (b < PB0 + PB1) ? 1 : 2;
    lb = b - ((which == 0) ? 0 : (which == 1) ? PB0 : PB0 + PB1);
}

__global__ void __launch_bounds__(256) scanA_kernel() {
    int which, lb;
    scan_map(blockIdx.x, which, lb);
    int n = (which == 0) ? N_ENT : (which == 1) ? N_USERS : N_ITEMS;
    const int* bins = (which == 0) ? g_bins_e : (which == 1) ? g_bins_r : g_bins_c;
    int base = lb * 2048;
    int sum = 0;
    for (int i = threadIdx.x; i < 2048; i += 256) {
        int idx = base + i;
        sum += (idx < n) ? bins[idx] : 0;
    }
    #pragma unroll
    for (int o = 16; o; o >>= 1) sum += __shfl_xor_sync(0xffffffffu, sum, o);
    __shared__ int ws[8];
    int lane = threadIdx.x & 31, wid = threadIdx.x >> 5;
    if (lane == 0) ws[wid] = sum;
    __syncthreads();
    if (threadIdx.x == 0) {
        int t = 0;
        #pragma unroll
        for (int i = 0; i < 8; i++) t += ws[i];
        g_part[blockIdx.x] = t;
    }
}

// scanC: per-block prefix over raw partials (scanB folded in)
__global__ void __launch_bounds__(256) scanC_kernel() {
    int which, lb;
    scan_map(blockIdx.x, which, lb);
    int n  = (which == 0) ? N_ENT : (which == 1) ? N_USERS : N_ITEMS;
    int nb = (which == 0) ? PB0   : (which == 1) ? PB1     : PB2;
    int pbase = (which == 0) ? 0  : (which == 1) ? PB0     : PB0 + PB1;
    const int* bins = (which == 0) ? g_bins_e : (which == 1) ? g_bins_r : g_bins_c;
    int* offs = (which == 0) ? g_eoff : (which == 1) ? g_roff : g_coff;
    int* cur  = (which == 0) ? g_cur_e : (which == 1) ? g_cur_r : g_cur_c;
    int base = lb * 2048;
    int lane = threadIdx.x & 31, wid = threadIdx.x >> 5;

    __shared__ int s_pref;
    if (wid == 0) {
        int p = 0;
        for (int i = lane; i < lb; i += 32) p += g_part[pbase + i];
        #pragma unroll
        for (int o = 16; o; o >>= 1) p += __shfl_xor_sync(0xffffffffu, p, o);
        if (lane == 0) {
            s_pref = p;
            if (lb == nb - 1) offs[n] = p + g_part[pbase + lb];
        }
    }

    int vals[8];
    int tsum = 0;
    #pragma unroll
    for (int k = 0; k < 8; k++) {
        int idx = base + threadIdx.x * 8 + k;
        vals[k] = (idx < n) ? bins[idx] : 0;
        tsum += vals[k];
    }
    int x = tsum;
    #pragma unroll
    for (int o = 1; o < 32; o <<= 1) {
        int t = __shfl_up_sync(0xffffffffu, x, o);
        if (lane >= o) x += t;
    }
    __shared__ int ws[8];
    if (lane == 31) ws[wid] = x;
    __syncthreads();
    int wpref = 0;
    for (int i = 0; i < wid; i++) wpref += ws[i];
    int acc = s_pref + wpref + x - tsum;
    #pragma unroll
    for (int k = 0; k < 8; k++) {
        int idx = base + threadIdx.x * 8 + k;
        if (idx < n) { offs[idx] = acc; cur[idx] = acc; }
        acc += vals[k];
    }
}

__global__ void scatter3_kernel(const int* __restrict__ head,
                                const int* __restrict__ tail,
                                const int* __restrict__ etype,
                                const int2* __restrict__ imat) {
    int i = blockIdx.x * blockDim.x + threadIdx.x;
    if (i < N_EDGES) {
        int h = head[i];
        int pos = atomicAdd(&g_cur_e[h], 1);
        g_te[pos] = make_int2(tail[i], etype[i]);
    }
    if (i < N_INTER) {
        int2 rc = imat[i];
        int pr = atomicAdd(&g_cur_r[rc.x], 1);
        g_rc[pr] = make_int2(rc.y, i);
        int pc = atomicAdd(&g_cur_c[rc.y], 1);
        g_crow[pc] = rc.x;
    }
}

// ---------------- KG aggregation (2 entities/warp) + item_agg fused ----------------
#define EBLK 6250   // 100000 entities / 16 per block
#define IBLK 3750   // 30000 items / 8 per block

__global__ void __launch_bounds__(256) entity_item_kernel(
    const float* __restrict__ ent, const float* __restrict__ relw,
    const float* __restrict__ b1, const float* __restrict__ b2,
    const float* __restrict__ ucf0,
    float* __restrict__ out_agg, float* __restrict__ out_item)
{
    int tid = threadIdx.x;
    int warp = tid >> 5, lane = tid & 31, hl = lane >> 4, q = lane & 15;

    if (blockIdx.x >= EBLK) {
        // -------- item_agg path --------
        int it = (blockIdx.x - EBLK) * 8 + warp;
        int s = g_coff[it], e = g_coff[it + 1];
        float4 acc = make_float4(0.f, 0.f, 0.f, 0.f);
        int j = s;
        #pragma unroll 2
        for (; j + 2 <= e; j += 2) {
            int r = g_crow[j + hl];
            float4 v = *(const float4*)&ucf0[(size_t)r * D + q * 4];
            acc.x += v.x; acc.y += v.y; acc.z += v.z; acc.w += v.w;
        }
        if (j < e && hl == 0) {
            int r = g_crow[j];
            float4 v = *(const float4*)&ucf0[(size_t)r * D + q * 4];
            acc.x += v.x; acc.y += v.y; acc.z += v.z; acc.w += v.w;
        }
        acc.x += __shfl_xor_sync(0xffffffffu, acc.x, 16);
        acc.y += __shfl_xor_sync(0xffffffffu, acc.y, 16);
        acc.z += __shfl_xor_sync(0xffffffffu, acc.z, 16);
        acc.w += __shfl_xor_sync(0xffffffffu, acc.w, 16);
        if (hl == 0) {
            float inv = 1.f / fmaxf((float)(e - s), 1.f);
            float4 r = make_float4(acc.x * inv, acc.y * inv, acc.z * inv, acc.w * inv);
            *(float4*)&out_item[(size_t)it * D + q * 4] = r;
        }
        return;
    }

    // -------- entity path --------
    __shared__ float sRel[N_REL * D];
    __shared__ float sMA[8][2][D];
    __shared__ float sMB[8][2][D];
    for (int i = tid; i < N_REL * D; i += 256) sRel[i] = relw[i];
    __syncthreads();

    int h = blockIdx.x * 16 + warp * 2 + hl;
    int s = g_eoff[h], e = g_eoff[h + 1];
    bool head_item = (h < N_ITEMS);

    float4 a1 = make_float4(0.f, 0.f, 0.f, 0.f), a2 = a1, ar = a1;
    int c1 = 0, c2 = 0;
    #pragma unroll 2
    for (int j = s; j < e; j++) {
        int2 tr = g_te[j];
        float4 te = *(const float4*)&ent[(size_t)tr.x * D + q * 4];
        float4 re = *(const float4*)&sRel[tr.y * D + q * 4];
        ar.x += re.x; ar.y += re.y; ar.z += re.z; ar.w += re.w;
        bool cross = head_item ^ (tr.x < N_ITEMS);
        if (cross) {
            a1.x += te.x * re.x; a1.y += te.y * re.y;
            a1.z += te.z * re.z; a1.w += te.w * re.w; c1++;
        } else {
            a2.x += te.x + re.x; a2.y += te.y + re.y;
            a2.z += te.z + re.z; a2.w += te.w + re.w; c2++;
        }
    }
    float inv1 = 1.f / fmaxf((float)c1, 1.f);
    float inv2 = 1.f / fmaxf((float)c2, 1.f);
    float invr = 1.f / fmaxf((float)(e - s), 1.f);

    if (head_item) {
        float4 kg = *(const float4*)&ent[(size_t)h * D + q * 4];
        float4 w = make_float4(ar.x * invr * kg.x, ar.y * invr * kg.y,
                               ar.z * invr * kg.z, ar.w * invr * kg.w);
        *(float4*)&g_wkg[(size_t)h * D + q * 4] = w;
    }

    *(float4*)&sMA[warp][hl][q * 4] = make_float4(a1.x * inv1, a1.y * inv1, a1.z * inv1, a1.w * inv1);
    *(float4*)&sMB[warp][hl][q * 4] = make_float4(a2.x * inv2, a2.y * inv2, a2.z * inv2, a2.w * inv2);
    __syncwarp();

    float4 o = *(const float4*)&b1[q * 4];
    float4 p = *(const float4*)&b2[q * 4];
    #pragma unroll 8
    for (int k = 0; k < D; k++) {
        float m1 = sMA[warp][hl][k];
        float m2 = sMB[warp][hl][k];
        float4 w1 = *(const float4*)&g_W1t[k * D + q * 4];
        float4 w2 = *(const float4*)&g_W2t[k * D + q * 4];
        o.x += m1 * w1.x; o.y += m1 * w1.y; o.z += m1 * w1.z; o.w += m1 * w1.w;
        p.x += m2 * w2.x; p.y += m2 * w2.y; p.z += m2 * w2.z; p.w += m2 * w2.w;
    }
    float4 r;
    r.x = (o.x >= 0.f ? o.x : 0.01f * o.x) * 0.5f + (p.x >= 0.f ? p.x : 0.01f * p.x) * 0.5f;
    r.y = (o.y >= 0.f ? o.y : 0.01f * o.y) * 0.5f + (p.y >= 0.f ? p.y : 0.01f * p.y) * 0.5f;
    r.z = (o.z >= 0.f ? o.z : 0.01f * o.z) * 0.5f + (p.z >= 0.f ? p.z : 0.01f * p.z) * 0.5f;
    r.w = (o.w >= 0.f ? o.w : 0.01f * o.w) * 0.5f + (p.w >= 0.f ? p.w : 0.01f * p.w) * 0.5f;
    *(float4*)&out_agg[(size_t)h * D + q * 4] = r;
}

// ---------------- fused 3-iteration CF attention: warp per user (no smem) ----------------
__global__ void __launch_bounds__(256) iter3_kernel(
    const float* __restrict__ user, const float* __restrict__ ucf0,
    const float* __restrict__ ent,  const float* __restrict__ icf,
    float* __restrict__ out_u, float* __restrict__ out_ucf,
    float* __restrict__ out_mask)
{
    int warp = threadIdx.x >> 5, lane = threadIdx.x & 31;
    int hl = lane >> 4, q = lane & 15;

    int gw = blockIdx.x * 8 + warp;   // 6250*8 = 50000 exact
    int s = g_roff[gw], e = g_roff[gw + 1];

    float4 u = *(const float4*)&user[(size_t)gw * D + q * 4];
    float4 c = *(const float4*)&ucf0[(size_t)gw * D + q * 4];

    #pragma unroll 1
    for (int it = 0; it < 3; it++) {
        // ---- pass 1: dots + softmax numerators ----
        float z = 0.f, zc = 0.f;
        int j = s;
        #pragma unroll 2
        for (; j + 2 <= e; j += 2) {
            int col = g_rc[j + hl].x;
            float4 w = *(const float4*)&g_wkg[(size_t)col * D + q * 4];
            float4 v = *(const float4*)&icf[(size_t)col * D + q * 4];
            float d1 = u.x * w.x + u.y * w.y + u.z * w.z + u.w * w.w;
            float d2 = c.x * v.x + c.y * v.y + c.z * v.z + c.w * v.w;
            #pragma unroll
            for (int o = 8; o; o >>= 1) {
                d1 += __shfl_xor_sync(0xffffffffu, d1, o);
                d2 += __shfl_xor_sync(0xffffffffu, d2, o);
            }
            if (q == 0) {
                float ep = __expf(fsigmoid(d1));
                float eq = __expf(fsigmoid(d2));
                z += ep; zc += eq;
                g_cu[j + hl] = ep;
                g_cc[j + hl] = eq;
            }
        }
        if (j < e) {
            int col = g_rc[j].x;
            float4 w = *(const float4*)&g_wkg[(size_t)col * D + q * 4];
            float4 v = *(const float4*)&icf[(size_t)col * D + q * 4];
            float d1 = u.x * w.x + u.y * w.y + u.z * w.z + u.w * w.w;
            float d2 = c.x * v.x + c.y * v.y + c.z * v.z + c.w * v.w;
            #pragma unroll
            for (int o = 8; o; o >>= 1) {
                d1 += __shfl_xor_sync(0xffffffffu, d1, o);
                d2 += __shfl_xor_sync(0xffffffffu, d2, o);
            }
            if (lane == 0) {
                float ep = __expf(fsigmoid(d1));
                float eq = __expf(fsigmoid(d2));
                z += ep; zc += eq;
                g_cu[j] = ep;
                g_cc[j] = eq;
            }
        }
        __syncwarp();
        #pragma unroll
        for (int o = 16; o; o >>= 1) {
            z  += __shfl_xor_sync(0xffffffffu, z, o);
            zc += __shfl_xor_sync(0xffffffffu, zc, o);
        }
        float iz  = (z  > 0.f) ? __fdividef(1.f, z)  : 0.f;
        float izc = (zc > 0.f) ? __fdividef(1.f, zc) : 0.f;

        // ---- mid: lane-parallel coefficients + mask ----
        for (int jj = s + lane; jj < e; jj += 32) {
            float pn = g_cu[jj] * iz;
            float qn = g_cc[jj] * izc;
            float m = (fabsf(fsigmoid(pn) - fsigmoid(qn)) < GAMMA_F) ? 1.f : 0.f;
            if (it == 2) out_mask[g_rc[jj].y] = m;
            g_cu[jj] = pn * m;
            g_cc[jj] = qn * m;
        }
        __syncwarp();

        // ---- pass 2: weighted sums ----
        float4 au = make_float4(0.f, 0.f, 0.f, 0.f), ac = au;
        j = s;
        #pragma unroll 2
        for (; j + 2 <= e; j += 2) {
            int jj = j + hl;
            int col = g_rc[jj].x;
            float cu = g_cu[jj], cc = g_cc[jj];
            float4 kg = *(const float4*)&ent[(size_t)col * D + q * 4];
            float4 v  = *(const float4*)&icf[(size_t)col * D + q * 4];
            au.x += cu * kg.x; au.y += cu * kg.y; au.z += cu * kg.z; au.w += cu * kg.w;
            ac.x += cc * v.x;  ac.y += cc * v.y;  ac.z += cc * v.z;  ac.w += cc * v.w;
        }
        if (j < e && hl == 0) {
            int col = g_rc[j].x;
            float cu = g_cu[j], cc = g_cc[j];
            float4 kg = *(const float4*)&ent[(size_t)col * D + q * 4];
            float4 v  = *(const float4*)&icf[(size_t)col * D + q * 4];
            au.x += cu * kg.x; au.y += cu * kg.y; au.z += cu * kg.z; au.w += cu * kg.w;
            ac.x += cc * v.x;  ac.y += cc * v.y;  ac.z += cc * v.z;  ac.w += cc * v.w;
        }
        au.x += __shfl_xor_sync(0xffffffffu, au.x, 16);
        au.y += __shfl_xor_sync(0xffffffffu, au.y, 16);
        au.z += __shfl_xor_sync(0xffffffffu, au.z, 16);
        au.w += __shfl_xor_sync(0xffffffffu, au.w, 16);
        ac.x += __shfl_xor_sync(0xffffffffu, ac.x, 16);
        ac.y += __shfl_xor_sync(0xffffffffu, ac.y, 16);
        ac.z += __shfl_xor_sync(0xffffffffu, ac.z, 16);
        ac.w += __shfl_xor_sync(0xffffffffu, ac.w, 16);

        if (it < 2) {
            float su = au.x * au.x + au.y * au.y + au.z * au.z + au.w * au.w;
            float sc = ac.x * ac.x + ac.y * ac.y + ac.z * ac.z + ac.w * ac.w;
            #pragma unroll
            for (int o = 8; o; o >>= 1) {
                su += __shfl_xor_sync(0xffffffffu, su, o);
                sc += __shfl_xor_sync(0xffffffffu, sc, o);
            }
            float inu = __fdividef(1.f, fmaxf(sqrtf(su), 1e-12f));
            float inc = __fdividef(1.f, fmaxf(sqrtf(sc), 1e-12f));
            u.x = au.x * inu; u.y = au.y * inu; u.z = au.z * inu; u.w = au.w * inu;
            c.x = ac.x * inc; c.y = ac.y * inc; c.z = ac.z * inc; c.w = ac.w * inc;
        } else if (hl == 0) {
            *(float4*)&out_u[(size_t)gw * D + q * 4]   = au;
            *(float4*)&out_ucf[(size_t)gw * D + q * 4] = ac;
        }
        __syncwarp();
    }
}

// ---------------- launch ----------------
extern "C" void kernel_launch(void* const* d_in, const int* in_sizes, int n_in,
                              void* d_out, int out_size) {
    const float* ent   = (const float*)d_in[0];
    const float* user  = (const float*)d_in[1];
    const float* ucf   = (const float*)d_in[2];
    const float* icf   = (const float*)d_in[3];
    const float* relw  = (const float*)d_in[4];
    const float* W1    = (const float*)d_in[5];
    const float* b1    = (const float*)d_in[6];
    const float* W2    = (const float*)d_in[7];
    const float* b2    = (const float*)d_in[8];
    const int*   eidx  = (const int*)d_in[9];     // [2, N_EDGES]
    const int*   etype = (const int*)d_in[10];
    const int*   imat  = (const int*)d_in[11];    // [N_INTER, 2]

    float* out      = (float*)d_out;
    float* out_ent  = out;
    float* out_u    = out_ent + (size_t)N_ENT * D;
    float* out_ucf  = out_u   + (size_t)N_USERS * D;
    float* out_item = out_ucf + (size_t)N_USERS * D;
    float* out_mask = out_item + (size_t)N_ITEMS * D;

    const int T = 256;
    zero3_kernel<<<(N_ENT + T - 1) / T, T>>>(W1, W2);
    hist3_kernel<<<(N_EDGES + T - 1) / T, T>>>(eidx, (const int2*)imat);
    scanA_kernel<<<PBT, T>>>();
    scanC_kernel<<<PBT, T>>>();
    scatter3_kernel<<<(N_EDGES + T - 1) / T, T>>>(eidx, eidx + N_EDGES, etype,
                                                  (const int2*)imat);

    entity_item_kernel<<<EBLK + IBLK, T>>>(ent, relw, b1, b2, ucf,
                                           out_ent, out_item);

    iter3_kernel<<<N_USERS / 8, T>>>(user, ucf, ent, icf,
                                     out_u, out_ucf, out_mask);
}